// round 1
// baseline (speedup 1.0000x reference)
#include <cuda_runtime.h>
#include <math.h>
#include <stdint.h>

#define N_    16
#define C_    64
#define F_    8
#define HW_   3136
#define HW4_  784            // HW_/4, rows are 16B aligned (3136*4 bytes)
#define NROWS (N_*C_*F_)     // 8192
#define ITER_ 128
#define OUT_  256
#define EPSV  1e-5

// ---------------- scratch (static device memory; rewritten fully each run) ----
__device__ float  d_top5[NROWS*5];
__device__ double d_rsum[NROWS];
__device__ double d_rsq [NROWS];
__device__ float  d_si  [N_*C_*7*20];     // attention output, conv1 input
__device__ float  d_x1  [N_*ITER_*7*10];  // conv1 output (pre-BN)
__device__ double d_p1s [N_*ITER_];
__device__ double d_p1q [N_*ITER_];
__device__ float  d_x2  [N_*OUT_*7*5];    // conv2 output (pre-BN)
__device__ double d_p2s [N_*OUT_];
__device__ double d_p2q [N_*OUT_];

// ---------------- helpers -----------------------------------------------------
__device__ __forceinline__ void ins5(float* kk, float key) {
    if (key > kk[4]) {
        kk[4] = key;
        if (kk[4] > kk[3]) { float t=kk[4]; kk[4]=kk[3]; kk[3]=t;
        if (kk[3] > kk[2]) { t=kk[3]; kk[3]=kk[2]; kk[2]=t;
        if (kk[2] > kk[1]) { t=kk[2]; kk[2]=kk[1]; kk[1]=t;
        if (kk[1] > kk[0]) { t=kk[1]; kk[1]=kk[0]; kk[0]=t; } } } }
    }
}

// merge two sorted-descending 5-lists, keep top 5 (in a)
__device__ __forceinline__ void merge5(float* a, const float* b) {
    float r[5]; int ia = 0, ib = 0;
    #pragma unroll
    for (int t = 0; t < 5; t++) {
        float av = a[ia], bv = b[ib];
        if (av >= bv) { r[t] = av; ia++; } else { r[t] = bv; ib++; }
    }
    #pragma unroll
    for (int t = 0; t < 5; t++) a[t] = r[t];
}

// ---------------- K1: fused single pass: per-row top5 (raw, keyed by sign(g)) +
// per-row sum / sumsq for channel BN statistics ---------------------------------
__global__ void __launch_bounds__(128) k1_top5(const float* __restrict__ h,
                                               const float* __restrict__ g0) {
    const int row = blockIdx.x;
    const int tid = threadIdx.x;
    const int c   = (row >> 3) & (C_ - 1);
    const float sel = (g0[c] >= 0.f) ? 1.f : -1.f;

    const float4* p = (const float4*)(h + (size_t)row * HW_);

    float kk[5];
    #pragma unroll
    for (int j = 0; j < 5; j++) kk[j] = -3.402823466e38f;
    float s = 0.f, q = 0.f;

    for (int i = tid; i < HW4_; i += 128) {
        float4 v = p[i];
        float x;
        x = v.x; s += x; q += x*x; ins5(kk, x*sel);
        x = v.y; s += x; q += x*x; ins5(kk, x*sel);
        x = v.z; s += x; q += x*x; ins5(kk, x*sel);
        x = v.w; s += x; q += x*x; ins5(kk, x*sel);
    }

    // warp reduce
    const unsigned m = 0xffffffffu;
    #pragma unroll
    for (int off = 16; off > 0; off >>= 1) {
        float ob[5];
        #pragma unroll
        for (int j = 0; j < 5; j++) ob[j] = __shfl_down_sync(m, kk[j], off);
        merge5(kk, ob);
        s += __shfl_down_sync(m, s, off);
        q += __shfl_down_sync(m, q, off);
    }

    __shared__ float wk[4][5];
    __shared__ float wsf[4], wqf[4];
    const int w = tid >> 5, l = tid & 31;
    if (l == 0) {
        #pragma unroll
        for (int j = 0; j < 5; j++) wk[w][j] = kk[j];
        wsf[w] = s; wqf[w] = q;
    }
    __syncthreads();
    if (tid == 0) {
        float fin[5];
        #pragma unroll
        for (int j = 0; j < 5; j++) fin[j] = wk[0][j];
        merge5(fin, wk[1]); merge5(fin, wk[2]); merge5(fin, wk[3]);
        #pragma unroll
        for (int j = 0; j < 5; j++) d_top5[row*5 + j] = fin[j] * sel;
        d_rsum[row] = (double)wsf[0] + (double)wsf[1] + (double)wsf[2] + (double)wsf[3];
        d_rsq [row] = (double)wqf[0] + (double)wqf[1] + (double)wqf[2] + (double)wqf[3];
    }
}

// ---------------- K3: per-(n,c) block: channel BN stats finalize + full
// attention pipeline down to si ------------------------------------------------
__global__ void __launch_bounds__(256) k3_attn(
    const float* __restrict__ g0,  const float* __restrict__ b0,
    const float* __restrict__ up_w, const float* __restrict__ up_b,
    const float* __restrict__ up2_w, const float* __restrict__ up2_b,
    const float* __restrict__ up3_w, const float* __restrict__ up3_b,
    const float* __restrict__ wW,   const float* __restrict__ wproj,
    const float* __restrict__ wW2,  const float* __restrict__ wproj2) {

    const int bid = blockIdx.x;     // n*64 + c
    const int tid = threadIdx.x;
    const int n = bid >> 6, c = bid & 63;

    __shared__ double s1[128], s2[128];
    __shared__ float  s_scale, s_shift;
    __shared__ float  sm_t[8][25], sm_u[8][25];
    __shared__ float  sm_s5[8][5], sm_att[8][5], sm_w5[8][5];
    __shared__ float  sm_cen[8][2];
    __shared__ float  sm_cen20[7][20], sm_u2p[7][20];
    __shared__ float  sm_s2[7], sm_att2[7];

    if (tid < 128) {
        int n2 = tid >> 3, f = tid & 7;
        int r = (n2*C_ + c)*F_ + f;
        s1[tid] = d_rsum[r];
        s2[tid] = d_rsq [r];
    }
    __syncthreads();
    for (int st = 64; st > 0; st >>= 1) {
        if (tid < st) { s1[tid] += s1[tid+st]; s2[tid] += s2[tid+st]; }
        __syncthreads();
    }
    if (tid == 0) {
        double cnt  = (double)(N_ * F_ * HW_);
        double mean = s1[0] / cnt;
        double var  = s2[0] / cnt - mean*mean;
        double inv  = rsqrt(var + EPSV);
        float  sc   = (float)((double)g0[c] * inv);
        s_scale = sc;
        s_shift = b0[c] - (float)mean * sc;
    }
    __syncthreads();

    const int f = tid >> 5, lane = tid & 31;   // 8 warps = 8 frames
    const int row = (n*C_ + c)*F_ + f;

    float v[5];
    #pragma unroll
    for (int j = 0; j < 5; j++) v[j] = d_top5[row*5 + j] * s_scale + s_shift;

    // t = top5 @ up2_w^T + up2_b      (25)
    if (lane < 25) {
        float a = up2_b[lane];
        #pragma unroll
        for (int j = 0; j < 5; j++) a += v[j] * up2_w[lane*5 + j];
        sm_t[f][lane] = a;
    }
    __syncwarp();
    // u = tanh(t @ wW)                (25)
    if (lane < 25) {
        float a = 0.f;
        #pragma unroll
        for (int k = 0; k < 25; k++) a += sm_t[f][k] * wW[k*25 + lane];
        sm_u[f][lane] = tanhf(a);
    }
    __syncwarp();
    // s = u @ wproj                    (5)
    if (lane < 5) {
        float a = 0.f;
        #pragma unroll
        for (int k = 0; k < 25; k++) a += sm_u[f][k] * wproj[k*5 + lane];
        sm_s5[f][lane] = a;
    }
    __syncwarp();
    // att = softmax(s); w5 = (t @ up3_w^T + up3_b) * att
    if (lane < 5) {
        float mx = sm_s5[f][0];
        #pragma unroll
        for (int j = 1; j < 5; j++) mx = fmaxf(mx, sm_s5[f][j]);
        float se = 0.f;
        #pragma unroll
        for (int j = 0; j < 5; j++) se += expf(sm_s5[f][j] - mx);
        float att = expf(sm_s5[f][lane] - mx) / se;
        sm_att[f][lane] = att;
        float a = up3_b[lane];
        #pragma unroll
        for (int k = 0; k < 25; k++) a += sm_t[f][k] * up3_w[lane*25 + k];
        sm_w5[f][lane] = a * att;
    }
    __syncwarp();
    // scored = w5 @ up2_w^T + up2_b; cen = scored @ coords
    float p0 = 0.f, p1 = 0.f;
    if (lane < 25) {
        float a = up2_b[lane];
        #pragma unroll
        for (int j = 0; j < 5; j++) a += sm_w5[f][j] * up2_w[lane*5 + j];
        p0 = a * (float)(lane / 5);
        p1 = a * (float)(lane % 5);
    }
    #pragma unroll
    for (int off = 16; off > 0; off >>= 1) {
        p0 += __shfl_down_sync(0xffffffffu, p0, off);
        p1 += __shfl_down_sync(0xffffffffu, p1, off);
    }
    if (lane == 0) { sm_cen[f][0] = p0; sm_cen[f][1] = p1; }
    __syncthreads();

    // frame diff -> up_w projection    (7x20)
    if (tid < 140) {
        int j = tid / 20, k = tid % 20;
        float d0 = sm_cen[j+1][0] - sm_cen[j][0];
        float d1 = sm_cen[j+1][1] - sm_cen[j][1];
        sm_cen20[j][k] = d0 * up_w[k*2] + d1 * up_w[k*2 + 1] + up_b[k];
    }
    __syncthreads();
    // u2 = tanh(wW2 @ cen20) * wproj2 (pre-multiplied for s2 reduction)
    if (tid < 140) {
        int i = tid / 20, k = tid % 20;
        float a = 0.f;
        #pragma unroll
        for (int j = 0; j < 7; j++) a += wW2[i*7 + j] * sm_cen20[j][k];
        sm_u2p[i][k] = tanhf(a) * wproj2[k];
    }
    __syncthreads();
    if (tid < 7) {
        float a = 0.f;
        #pragma unroll
        for (int k = 0; k < 20; k++) a += sm_u2p[tid][k];
        sm_s2[tid] = a;
    }
    __syncthreads();
    if (tid < 7) {
        float mx = sm_s2[0];
        #pragma unroll
        for (int i = 1; i < 7; i++) mx = fmaxf(mx, sm_s2[i]);
        float se = 0.f;
        #pragma unroll
        for (int i = 0; i < 7; i++) se += expf(sm_s2[i] - mx);
        sm_att2[tid] = expf(sm_s2[tid] - mx) / se;
    }
    __syncthreads();
    if (tid < 140) {
        int j = tid / 20, k = tid % 20;
        d_si[(bid*7 + j)*20 + k] = sm_cen20[j][k] * sm_att2[j];
    }
}

// ---------------- K4: conv1 (64->128, k=(1,3), s=(1,2), p=(0,1)) + BN1 partials
__global__ void __launch_bounds__(256) k4_conv1(const float* __restrict__ w1) {
    __shared__ float s_si[C_*140];   // 8960 floats (35 KB)
    __shared__ float s_w[8*192];     // 1536 floats

    const int bid = blockIdx.x, tid = threadIdx.x;
    const int n = bid >> 4, gid = bid & 15;
    const int ocbase = gid * 8;

    const float* src = d_si + n * (C_*140);
    for (int i = tid; i < C_*140; i += 256) s_si[i] = src[i];
    for (int i = tid; i < 8*192;  i += 256) s_w[i]  = w1[ocbase*192 + i];
    __syncthreads();

    const int wrp = tid >> 5, lane = tid & 31;
    const int oc = ocbase + wrp;
    float ssum = 0.f, ssq = 0.f;

    for (int o = lane; o < 70; o += 32) {
        int i = o / 10, ow = o % 10;
        int iw0 = 2*ow - 1;
        float acc = 0.f;
        const float* wp = &s_w[wrp*192];
        for (int ic = 0; ic < 64; ic++) {
            const float* xp = &s_si[ic*140 + i*20];
            #pragma unroll
            for (int kw = 0; kw < 3; kw++) {
                int iw = iw0 + kw;
                if (iw >= 0 && iw < 20) acc += xp[iw] * wp[ic*3 + kw];
            }
        }
        d_x1[((n*ITER_ + oc)*7 + i)*10 + ow] = acc;
        ssum += acc; ssq += acc*acc;
    }
    #pragma unroll
    for (int off = 16; off > 0; off >>= 1) {
        ssum += __shfl_down_sync(0xffffffffu, ssum, off);
        ssq  += __shfl_down_sync(0xffffffffu, ssq,  off);
    }
    if (lane == 0) {
        d_p1s[n*ITER_ + oc] = (double)ssum;
        d_p1q[n*ITER_ + oc] = (double)ssq;
    }
}

// ---------------- K6: BN1 finalize(inline)+tanh, conv2 (128->256), BN2 partials
__global__ void __launch_bounds__(512) k6_conv2(const float* __restrict__ w2,
                                                const float* __restrict__ g1,
                                                const float* __restrict__ b1) {
    extern __shared__ float sm[];
    float* s_x  = sm;            // 8960
    float* s_w  = sm + 8960;     // 6144
    float* s_sc = sm + 15104;    // 128
    float* s_sh = sm + 15232;    // 128

    const int bid = blockIdx.x, tid = threadIdx.x;
    const int n = bid >> 4, gid = bid & 15;
    const int ocbase = gid * 16;

    if (tid < 128) {
        double S = 0.0, Q = 0.0;
        for (int n2 = 0; n2 < 16; n2++) { S += d_p1s[n2*ITER_ + tid]; Q += d_p1q[n2*ITER_ + tid]; }
        double cnt = (double)(N_ * 7 * 10);
        double mean = S / cnt;
        double var  = Q / cnt - mean*mean;
        double inv  = rsqrt(var + EPSV);
        float sc = (float)((double)g1[tid] * inv);
        s_sc[tid] = sc;
        s_sh[tid] = b1[tid] - (float)mean * sc;
    }
    for (int i = tid; i < 16*384; i += 512) s_w[i] = w2[ocbase*384 + i];
    __syncthreads();

    const float* xs = d_x1 + n * (ITER_*70);
    for (int i = tid; i < ITER_*70; i += 512) {
        int ic = i / 70;
        s_x[i] = tanhf(xs[i] * s_sc[ic] + s_sh[ic]);
    }
    __syncthreads();

    const int wrp = tid >> 5, lane = tid & 31;
    const int oc = ocbase + wrp;
    float ssum = 0.f, ssq = 0.f;

    for (int o = lane; o < 35; o += 32) {
        int i = o / 5, ow = o % 5;
        int iw0 = 2*ow - 1;
        float acc = 0.f;
        const float* wp = &s_w[wrp*384];
        for (int ic = 0; ic < 128; ic++) {
            const float* xp = &s_x[ic*70 + i*10];
            #pragma unroll
            for (int kw = 0; kw < 3; kw++) {
                int iw = iw0 + kw;
                if (iw >= 0 && iw < 10) acc += xp[iw] * wp[ic*3 + kw];
            }
        }
        d_x2[((n*OUT_ + oc)*7 + i)*5 + ow] = acc;
        ssum += acc; ssq += acc*acc;
    }
    #pragma unroll
    for (int off = 16; off > 0; off >>= 1) {
        ssum += __shfl_down_sync(0xffffffffu, ssum, off);
        ssq  += __shfl_down_sync(0xffffffffu, ssq,  off);
    }
    if (lane == 0) {
        d_p2s[n*OUT_ + oc] = (double)ssum;
        d_p2q[n*OUT_ + oc] = (double)ssq;
    }
}

// ---------------- K8: BN2 finalize(inline) + tanh + width-mean -> out ---------
__global__ void __launch_bounds__(128) k8_final(const float* __restrict__ g2,
                                                const float* __restrict__ b2,
                                                float* __restrict__ out) {
    const int oc = blockIdx.x, tid = threadIdx.x;
    __shared__ float s_sc, s_sh;
    if (tid == 0) {
        double S = 0.0, Q = 0.0;
        for (int n2 = 0; n2 < 16; n2++) { S += d_p2s[n2*OUT_ + oc]; Q += d_p2q[n2*OUT_ + oc]; }
        double cnt = (double)(N_ * 7 * 5);
        double mean = S / cnt;
        double var  = Q / cnt - mean*mean;
        double inv  = rsqrt(var + EPSV);
        float sc = (float)((double)g2[oc] * inv);
        s_sc = sc;
        s_sh = b2[oc] - (float)mean * sc;
    }
    __syncthreads();
    if (tid < 112) {
        int n = tid / 7, i = tid % 7;
        const float* xp = &d_x2[((n*OUT_ + oc)*7 + i)*5];
        float a = 0.f;
        #pragma unroll
        for (int w = 0; w < 5; w++) a += tanhf(xp[w] * s_sc + s_sh);
        out[(n*OUT_ + oc)*7 + i] = a * 0.2f;
    }
}

// ---------------- launcher ----------------------------------------------------
extern "C" void kernel_launch(void* const* d_in, const int* in_sizes, int n_in,
                              void* d_out, int out_size) {
    (void)in_sizes; (void)n_in; (void)out_size;
    const float* h      = (const float*)d_in[0];
    const float* g0     = (const float*)d_in[1];
    const float* b0     = (const float*)d_in[2];
    const float* up_w   = (const float*)d_in[3];
    const float* up_b   = (const float*)d_in[4];
    const float* up2_w  = (const float*)d_in[5];
    const float* up2_b  = (const float*)d_in[6];
    const float* up3_w  = (const float*)d_in[7];
    const float* up3_b  = (const float*)d_in[8];
    const float* wW     = (const float*)d_in[9];
    const float* wproj  = (const float*)d_in[10];
    const float* wW2    = (const float*)d_in[11];
    const float* wproj2 = (const float*)d_in[12];
    const float* w1     = (const float*)d_in[13];
    const float* g1     = (const float*)d_in[14];
    const float* b1     = (const float*)d_in[15];
    const float* w2     = (const float*)d_in[16];
    const float* g2     = (const float*)d_in[17];
    const float* b2     = (const float*)d_in[18];
    float* out = (float*)d_out;

    cudaFuncSetAttribute(k6_conv2, cudaFuncAttributeMaxDynamicSharedMemorySize, 15360*4);

    k1_top5<<<NROWS, 128>>>(h, g0);
    k3_attn<<<N_*C_, 256>>>(g0, b0, up_w, up_b, up2_w, up2_b, up3_w, up3_b,
                            wW, wproj, wW2, wproj2);
    k4_conv1<<<256, 256>>>(w1);
    k6_conv2<<<256, 512, 15360*4>>>(w2, g1, b1);
    k8_final<<<OUT_, 128>>>(g2, b2, out);
}

// round 2
// speedup vs baseline: 1.1912x; 1.1912x over previous
#include <cuda_runtime.h>
#include <math.h>
#include <stdint.h>

#define N_    16
#define C_    64
#define F_    8
#define HW_   3136
#define HW4_  784            // HW_/4, rows are 16B aligned (3136*4 bytes)
#define NROWS (N_*C_*F_)     // 8192
#define ITER_ 128
#define OUT_  256
#define EPSV  1e-5

// ---------------- scratch (static device memory; rewritten fully each run) ----
__device__ float  d_top5[NROWS*5];
__device__ double d_rsum[NROWS];
__device__ double d_rsq [NROWS];
__device__ float  d_si  [N_*C_*7*20];     // attention output, conv1 input
__device__ float  d_x1  [N_*ITER_*7*10];  // conv1 output (pre-BN)
__device__ double d_p1s [N_*ITER_];
__device__ double d_p1q [N_*ITER_];
__device__ float  d_x2  [N_*OUT_*7*5];    // conv2 output (pre-BN)
__device__ double d_p2s [N_*OUT_];
__device__ double d_p2q [N_*OUT_];

// ---------------- helpers -----------------------------------------------------
__device__ __forceinline__ float ftanh(float x) {
    float y;
    asm("tanh.approx.f32 %0, %1;" : "=f"(y) : "f"(x));
    return y;
}

__device__ __forceinline__ void ins5(float* kk, float key) {
    if (key > kk[4]) {
        kk[4] = key;
        if (kk[4] > kk[3]) { float t=kk[4]; kk[4]=kk[3]; kk[3]=t;
        if (kk[3] > kk[2]) { t=kk[3]; kk[3]=kk[2]; kk[2]=t;
        if (kk[2] > kk[1]) { t=kk[2]; kk[2]=kk[1]; kk[1]=t;
        if (kk[1] > kk[0]) { t=kk[1]; kk[1]=kk[0]; kk[0]=t; } } } }
    }
}

// merge two sorted-descending 5-lists, keep top 5 (in a)
__device__ __forceinline__ void merge5(float* a, const float* b) {
    float r[5]; int ia = 0, ib = 0;
    #pragma unroll
    for (int t = 0; t < 5; t++) {
        float av = a[ia], bv = b[ib];
        if (av >= bv) { r[t] = av; ia++; } else { r[t] = bv; ib++; }
    }
    #pragma unroll
    for (int t = 0; t < 5; t++) a[t] = r[t];
}

// ---------------- K1: fused single pass: per-row top5 (raw, keyed by sign(g)) +
// per-row sum / sumsq for channel BN statistics ---------------------------------
__global__ void __launch_bounds__(128) k1_top5(const float* __restrict__ h,
                                               const float* __restrict__ g0) {
    const int row = blockIdx.x;
    const int tid = threadIdx.x;
    const int c   = (row >> 3) & (C_ - 1);
    const float sel = (g0[c] >= 0.f) ? 1.f : -1.f;

    const float4* p = (const float4*)(h + (size_t)row * HW_);

    float kk[5];
    #pragma unroll
    for (int j = 0; j < 5; j++) kk[j] = -3.402823466e38f;
    float s = 0.f, q = 0.f;

    #pragma unroll 3
    for (int i = tid; i < HW4_; i += 128) {
        float4 v = p[i];
        float x;
        x = v.x; s += x; q += x*x; ins5(kk, x*sel);
        x = v.y; s += x; q += x*x; ins5(kk, x*sel);
        x = v.z; s += x; q += x*x; ins5(kk, x*sel);
        x = v.w; s += x; q += x*x; ins5(kk, x*sel);
    }

    // warp reduce
    const unsigned m = 0xffffffffu;
    #pragma unroll
    for (int off = 16; off > 0; off >>= 1) {
        float ob[5];
        #pragma unroll
        for (int j = 0; j < 5; j++) ob[j] = __shfl_down_sync(m, kk[j], off);
        merge5(kk, ob);
        s += __shfl_down_sync(m, s, off);
        q += __shfl_down_sync(m, q, off);
    }

    __shared__ float wk[4][5];
    __shared__ float wsf[4], wqf[4];
    const int w = tid >> 5, l = tid & 31;
    if (l == 0) {
        #pragma unroll
        for (int j = 0; j < 5; j++) wk[w][j] = kk[j];
        wsf[w] = s; wqf[w] = q;
    }
    __syncthreads();
    if (tid == 0) {
        float fin[5];
        #pragma unroll
        for (int j = 0; j < 5; j++) fin[j] = wk[0][j];
        merge5(fin, wk[1]); merge5(fin, wk[2]); merge5(fin, wk[3]);
        #pragma unroll
        for (int j = 0; j < 5; j++) d_top5[row*5 + j] = fin[j] * sel;
        d_rsum[row] = (double)wsf[0] + (double)wsf[1] + (double)wsf[2] + (double)wsf[3];
        d_rsq [row] = (double)wqf[0] + (double)wqf[1] + (double)wqf[2] + (double)wqf[3];
    }
}

// ---------------- K3: per-(n,c) block: channel BN stats finalize + full
// attention pipeline down to si ------------------------------------------------
__global__ void __launch_bounds__(256) k3_attn(
    const float* __restrict__ g0,  const float* __restrict__ b0,
    const float* __restrict__ up_w, const float* __restrict__ up_b,
    const float* __restrict__ up2_w, const float* __restrict__ up2_b,
    const float* __restrict__ up3_w, const float* __restrict__ up3_b,
    const float* __restrict__ wW,   const float* __restrict__ wproj,
    const float* __restrict__ wW2,  const float* __restrict__ wproj2) {

    const int bid = blockIdx.x;     // n*64 + c
    const int tid = threadIdx.x;
    const int n = bid >> 6, c = bid & 63;

    __shared__ double s1[128], s2[128];
    __shared__ float  s_scale, s_shift;
    __shared__ float  sm_t[8][25], sm_u[8][25];
    __shared__ float  sm_s5[8][5], sm_att[8][5], sm_w5[8][5];
    __shared__ float  sm_cen[8][2];
    __shared__ float  sm_cen20[7][20], sm_u2p[7][20];
    __shared__ float  sm_s2[7], sm_att2[7];

    if (tid < 128) {
        int n2 = tid >> 3, f = tid & 7;
        int r = (n2*C_ + c)*F_ + f;
        s1[tid] = d_rsum[r];
        s2[tid] = d_rsq [r];
    }
    __syncthreads();
    for (int st = 64; st > 0; st >>= 1) {
        if (tid < st) { s1[tid] += s1[tid+st]; s2[tid] += s2[tid+st]; }
        __syncthreads();
    }
    if (tid == 0) {
        double cnt  = (double)(N_ * F_ * HW_);
        double mean = s1[0] / cnt;
        double var  = s2[0] / cnt - mean*mean;
        double inv  = rsqrt(var + EPSV);
        float  sc   = (float)((double)g0[c] * inv);
        s_scale = sc;
        s_shift = b0[c] - (float)mean * sc;
    }
    __syncthreads();

    const int f = tid >> 5, lane = tid & 31;   // 8 warps = 8 frames
    const int row = (n*C_ + c)*F_ + f;

    float v[5];
    #pragma unroll
    for (int j = 0; j < 5; j++) v[j] = d_top5[row*5 + j] * s_scale + s_shift;

    // t = top5 @ up2_w^T + up2_b      (25)
    if (lane < 25) {
        float a = up2_b[lane];
        #pragma unroll
        for (int j = 0; j < 5; j++) a += v[j] * up2_w[lane*5 + j];
        sm_t[f][lane] = a;
    }
    __syncwarp();
    // u = tanh(t @ wW)                (25)
    if (lane < 25) {
        float a = 0.f;
        #pragma unroll
        for (int k = 0; k < 25; k++) a += sm_t[f][k] * wW[k*25 + lane];
        sm_u[f][lane] = tanhf(a);
    }
    __syncwarp();
    // s = u @ wproj                    (5)
    if (lane < 5) {
        float a = 0.f;
        #pragma unroll
        for (int k = 0; k < 25; k++) a += sm_u[f][k] * wproj[k*5 + lane];
        sm_s5[f][lane] = a;
    }
    __syncwarp();
    // att = softmax(s); w5 = (t @ up3_w^T + up3_b) * att
    if (lane < 5) {
        float mx = sm_s5[f][0];
        #pragma unroll
        for (int j = 1; j < 5; j++) mx = fmaxf(mx, sm_s5[f][j]);
        float se = 0.f;
        #pragma unroll
        for (int j = 0; j < 5; j++) se += expf(sm_s5[f][j] - mx);
        float att = expf(sm_s5[f][lane] - mx) / se;
        sm_att[f][lane] = att;
        float a = up3_b[lane];
        #pragma unroll
        for (int k = 0; k < 25; k++) a += sm_t[f][k] * up3_w[lane*25 + k];
        sm_w5[f][lane] = a * att;
    }
    __syncwarp();
    // scored = w5 @ up2_w^T + up2_b; cen = scored @ coords
    float p0 = 0.f, p1 = 0.f;
    if (lane < 25) {
        float a = up2_b[lane];
        #pragma unroll
        for (int j = 0; j < 5; j++) a += sm_w5[f][j] * up2_w[lane*5 + j];
        p0 = a * (float)(lane / 5);
        p1 = a * (float)(lane % 5);
    }
    #pragma unroll
    for (int off = 16; off > 0; off >>= 1) {
        p0 += __shfl_down_sync(0xffffffffu, p0, off);
        p1 += __shfl_down_sync(0xffffffffu, p1, off);
    }
    if (lane == 0) { sm_cen[f][0] = p0; sm_cen[f][1] = p1; }
    __syncthreads();

    // frame diff -> up_w projection    (7x20)
    if (tid < 140) {
        int j = tid / 20, k = tid % 20;
        float d0 = sm_cen[j+1][0] - sm_cen[j][0];
        float d1 = sm_cen[j+1][1] - sm_cen[j][1];
        sm_cen20[j][k] = d0 * up_w[k*2] + d1 * up_w[k*2 + 1] + up_b[k];
    }
    __syncthreads();
    // u2 = tanh(wW2 @ cen20) * wproj2 (pre-multiplied for s2 reduction)
    if (tid < 140) {
        int i = tid / 20, k = tid % 20;
        float a = 0.f;
        #pragma unroll
        for (int j = 0; j < 7; j++) a += wW2[i*7 + j] * sm_cen20[j][k];
        sm_u2p[i][k] = tanhf(a) * wproj2[k];
    }
    __syncthreads();
    if (tid < 7) {
        float a = 0.f;
        #pragma unroll
        for (int k = 0; k < 20; k++) a += sm_u2p[tid][k];
        sm_s2[tid] = a;
    }
    __syncthreads();
    if (tid < 7) {
        float mx = sm_s2[0];
        #pragma unroll
        for (int i = 1; i < 7; i++) mx = fmaxf(mx, sm_s2[i]);
        float se = 0.f;
        #pragma unroll
        for (int i = 0; i < 7; i++) se += expf(sm_s2[i] - mx);
        sm_att2[tid] = expf(sm_s2[tid] - mx) / se;
    }
    __syncthreads();
    if (tid < 140) {
        int j = tid / 20, k = tid % 20;
        d_si[(bid*7 + j)*20 + k] = sm_cen20[j][k] * sm_att2[j];
    }
}

// ---------------- K4: conv1 (64->128, k=(1,3), s=(1,2), p=(0,1)) + BN1 partials
// Register-blocked: 1 thread = one (oc, i) row, 10 outputs in registers.
__global__ void __launch_bounds__(128) k4_conv1(const float* __restrict__ w1) {
    __shared__ float s_si[C_*140];   // 8960 floats (35 KB)
    __shared__ float s_w[16*192];    // 3072 floats
    __shared__ float sp[112], sq[112];

    const int bid = blockIdx.x, tid = threadIdx.x;
    const int n = bid >> 3, gid = bid & 7;
    const int ocbase = gid * 16;

    const float* src = d_si + n * (C_*140);
    for (int i = tid; i < C_*140; i += 128) s_si[i] = src[i];
    for (int i = tid; i < 16*192; i += 128) s_w[i]  = w1[ocbase*192 + i];
    __syncthreads();

    if (tid < 112) {
        const int ocl = tid / 7, i = tid % 7;
        const int oc = ocbase + ocl;
        float acc[10];
        #pragma unroll
        for (int j = 0; j < 10; j++) acc[j] = 0.f;
        const float* wp = &s_w[ocl*192];

        #pragma unroll 4
        for (int ic = 0; ic < 64; ic++) {
            const float* xp = &s_si[ic*140 + i*20];
            float4 v0 = *(const float4*)(xp);
            float4 v1 = *(const float4*)(xp + 4);
            float4 v2 = *(const float4*)(xp + 8);
            float4 v3 = *(const float4*)(xp + 12);
            float4 v4 = *(const float4*)(xp + 16);
            float x[20] = {v0.x,v0.y,v0.z,v0.w, v1.x,v1.y,v1.z,v1.w,
                           v2.x,v2.y,v2.z,v2.w, v3.x,v3.y,v3.z,v3.w,
                           v4.x,v4.y,v4.z,v4.w};
            float w0 = wp[ic*3], wv1 = wp[ic*3+1], wv2 = wp[ic*3+2];
            acc[0] += x[0]*wv1 + x[1]*wv2;
            #pragma unroll
            for (int ow = 1; ow < 10; ow++)
                acc[ow] += x[2*ow-1]*w0 + x[2*ow]*wv1 + x[2*ow+1]*wv2;
        }
        float ssum = 0.f, ssq = 0.f;
        float* op = &d_x1[((n*ITER_ + oc)*7 + i)*10];
        #pragma unroll
        for (int ow = 0; ow < 10; ow++) {
            op[ow] = acc[ow]; ssum += acc[ow]; ssq += acc[ow]*acc[ow];
        }
        sp[tid] = ssum; sq[tid] = ssq;
    }
    __syncthreads();
    if (tid < 16) {
        double S = 0.0, Q = 0.0;
        #pragma unroll
        for (int j = 0; j < 7; j++) { S += sp[tid*7+j]; Q += sq[tid*7+j]; }
        d_p1s[n*ITER_ + ocbase + tid] = S;
        d_p1q[n*ITER_ + ocbase + tid] = Q;
    }
}

// ---------------- K6: BN1 finalize(inline)+fast tanh staging, conv2 (128->256),
// BN2 partials. Register-blocked like k4; x rows padded to stride 12 in smem.
__global__ void __launch_bounds__(128) k6_conv2(const float* __restrict__ w2,
                                                const float* __restrict__ g1,
                                                const float* __restrict__ b1) {
    extern __shared__ float sm[];
    float* s_x  = sm;            // 128*84 = 10752 (rows of 10, padded to 12)
    float* s_w  = sm + 10752;    // 16*384 = 6144
    float* s_sc = sm + 16896;    // 128
    float* s_sh = sm + 17024;    // 128
    float* sp   = sm + 17152;    // 112
    float* sq   = sm + 17264;    // 112   total 17376 floats

    const int bid = blockIdx.x, tid = threadIdx.x;
    const int n = bid >> 4, gid = bid & 15;
    const int ocbase = gid * 16;

    // BN1 stats finalize (all 128 channels, every block)
    {
        double S = 0.0, Q = 0.0;
        #pragma unroll
        for (int n2 = 0; n2 < 16; n2++) { S += d_p1s[n2*ITER_ + tid]; Q += d_p1q[n2*ITER_ + tid]; }
        double cnt  = (double)(N_ * 7 * 10);
        double mean = S / cnt;
        double var  = Q / cnt - mean*mean;
        double inv  = rsqrt(var + EPSV);
        float sc = (float)((double)g1[tid] * inv);
        s_sc[tid] = sc;
        s_sh[tid] = b1[tid] - (float)mean * sc;
    }
    for (int i = tid; i < 16*384; i += 128) s_w[i] = w2[ocbase*384 + i];
    __syncthreads();

    // stage BN1+tanh input, padded layout [ic][i][0..9] stride 12
    const float* xs = d_x1 + n * (ITER_*70);
    for (int idx = tid; idx < ITER_*70; idx += 128) {
        int ic = idx / 70, r = idx - ic*70;
        int i = r / 10, ow = r - i*10;
        s_x[ic*84 + i*12 + ow] = ftanh(xs[idx] * s_sc[ic] + s_sh[ic]);
    }
    __syncthreads();

    if (tid < 112) {
        const int ocl = tid / 7, i = tid % 7;
        const int oc = ocbase + ocl;
        float acc[5];
        #pragma unroll
        for (int j = 0; j < 5; j++) acc[j] = 0.f;
        const float* wp = &s_w[ocl*384];

        #pragma unroll 4
        for (int ic = 0; ic < 128; ic++) {
            const float* xp = &s_x[ic*84 + i*12];
            float4 v0 = *(const float4*)(xp);
            float4 v1 = *(const float4*)(xp + 4);
            float2 v2 = *(const float2*)(xp + 8);
            float x[10] = {v0.x,v0.y,v0.z,v0.w, v1.x,v1.y,v1.z,v1.w, v2.x,v2.y};
            float w0 = wp[ic*3], wv1 = wp[ic*3+1], wv2 = wp[ic*3+2];
            acc[0] += x[0]*wv1 + x[1]*wv2;
            #pragma unroll
            for (int ow = 1; ow < 5; ow++)
                acc[ow] += x[2*ow-1]*w0 + x[2*ow]*wv1 + x[2*ow+1]*wv2;
        }
        float ssum = 0.f, ssq = 0.f;
        float* op = &d_x2[((n*OUT_ + oc)*7 + i)*5];
        #pragma unroll
        for (int ow = 0; ow < 5; ow++) {
            op[ow] = acc[ow]; ssum += acc[ow]; ssq += acc[ow]*acc[ow];
        }
        sp[tid] = ssum; sq[tid] = ssq;
    }
    __syncthreads();
    if (tid < 16) {
        double S = 0.0, Q = 0.0;
        #pragma unroll
        for (int j = 0; j < 7; j++) { S += sp[tid*7+j]; Q += sq[tid*7+j]; }
        d_p2s[n*OUT_ + ocbase + tid] = S;
        d_p2q[n*OUT_ + ocbase + tid] = Q;
    }
}

// ---------------- K8: BN2 finalize(inline) + tanh + width-mean -> out ---------
__global__ void __launch_bounds__(128) k8_final(const float* __restrict__ g2,
                                                const float* __restrict__ b2,
                                                float* __restrict__ out) {
    const int oc = blockIdx.x, tid = threadIdx.x;
    __shared__ float s_sc, s_sh;
    if (tid == 0) {
        double S = 0.0, Q = 0.0;
        for (int n2 = 0; n2 < 16; n2++) { S += d_p2s[n2*OUT_ + oc]; Q += d_p2q[n2*OUT_ + oc]; }
        double cnt = (double)(N_ * 7 * 5);
        double mean = S / cnt;
        double var  = Q / cnt - mean*mean;
        double inv  = rsqrt(var + EPSV);
        float sc = (float)((double)g2[oc] * inv);
        s_sc = sc;
        s_sh = b2[oc] - (float)mean * sc;
    }
    __syncthreads();
    if (tid < 112) {
        int n = tid / 7, i = tid % 7;
        const float* xp = &d_x2[((n*OUT_ + oc)*7 + i)*5];
        float a = 0.f;
        #pragma unroll
        for (int w = 0; w < 5; w++) a += tanhf(xp[w] * s_sc + s_sh);
        out[(n*OUT_ + oc)*7 + i] = a * 0.2f;
    }
}

// ---------------- launcher ----------------------------------------------------
extern "C" void kernel_launch(void* const* d_in, const int* in_sizes, int n_in,
                              void* d_out, int out_size) {
    (void)in_sizes; (void)n_in; (void)out_size;
    const float* h      = (const float*)d_in[0];
    const float* g0     = (const float*)d_in[1];
    const float* b0     = (const float*)d_in[2];
    const float* up_w   = (const float*)d_in[3];
    const float* up_b   = (const float*)d_in[4];
    const float* up2_w  = (const float*)d_in[5];
    const float* up2_b  = (const float*)d_in[6];
    const float* up3_w  = (const float*)d_in[7];
    const float* up3_b  = (const float*)d_in[8];
    const float* wW     = (const float*)d_in[9];
    const float* wproj  = (const float*)d_in[10];
    const float* wW2    = (const float*)d_in[11];
    const float* wproj2 = (const float*)d_in[12];
    const float* w1     = (const float*)d_in[13];
    const float* g1     = (const float*)d_in[14];
    const float* b1     = (const float*)d_in[15];
    const float* w2     = (const float*)d_in[16];
    const float* g2     = (const float*)d_in[17];
    const float* b2     = (const float*)d_in[18];
    float* out = (float*)d_out;

    cudaFuncSetAttribute(k6_conv2, cudaFuncAttributeMaxDynamicSharedMemorySize, 17376*4);

    k1_top5<<<NROWS, 128>>>(h, g0);
    k3_attn<<<N_*C_, 256>>>(g0, b0, up_w, up_b, up2_w, up2_b, up3_w, up3_b,
                            wW, wproj, wW2, wproj2);
    k4_conv1<<<128, 128>>>(w1);
    k6_conv2<<<256, 128, 17376*4>>>(w2, g1, b1);
    k8_final<<<OUT_, 128>>>(g2, b2, out);
}